// round 2
// baseline (speedup 1.0000x reference)
#include <cuda_runtime.h>

#define M_TOT   8192
#define DM      1024
#define N_HEADS 16
#define HD      64
#define SEQ     2048

// Scratch (device globals: no allocation allowed in kernel_launch)
__device__ float g_Q[M_TOT * DM];
__device__ float g_K[M_TOT * DM];
__device__ float g_V[M_TOT * DM];
__device__ float g_A[M_TOT * DM];

// ---------------------------------------------------------------------------
// Generic GEMM: C = A @ W^T + bias.  A:[M][K], W:[N][K], C:[M][N], K=N=1024.
// 128x128 macro tile, BK=32, 256 threads, 8x8 per-thread register tile.
// blockIdx.z selects among up to 3 (W, bias, C) triples (fused QKV launch).
// ---------------------------------------------------------------------------
__global__ __launch_bounds__(256) void gemm_xwt_kernel(
    const float* __restrict__ A,
    const float* __restrict__ W0, const float* __restrict__ W1, const float* __restrict__ W2,
    const float* __restrict__ b0, const float* __restrict__ b1, const float* __restrict__ b2,
    float* __restrict__ C0, float* __restrict__ C1, float* __restrict__ C2)
{
    __shared__ float As[32][132];   // [k][m], padded
    __shared__ float Bs[32][132];   // [k][n], padded

    const int z = blockIdx.z;
    const float* W    = (z == 0) ? W0 : (z == 1) ? W1 : W2;
    const float* bias = (z == 0) ? b0 : (z == 1) ? b1 : b2;
    float*       C    = (z == 0) ? C0 : (z == 1) ? C1 : C2;

    const int t  = threadIdx.x;
    const int tx = t & 15;
    const int ty = t >> 4;
    const int bm = blockIdx.x * 128;
    const int bn = blockIdx.y * 128;

    float acc[8][8];
#pragma unroll
    for (int i = 0; i < 8; i++)
#pragma unroll
        for (int j = 0; j < 8; j++) acc[i][j] = 0.f;

    for (int k0 = 0; k0 < DM; k0 += 32) {
#pragma unroll
        for (int i = 0; i < 4; i++) {
            int idx = t + i * 256;
            int row = idx >> 3;          // 0..127
            int kf  = (idx & 7) << 2;    // 0,4,..,28
            float4 va = *(const float4*)(A + (size_t)(bm + row) * DM + k0 + kf);
            As[kf + 0][row] = va.x; As[kf + 1][row] = va.y;
            As[kf + 2][row] = va.z; As[kf + 3][row] = va.w;
            float4 vb = *(const float4*)(W + (size_t)(bn + row) * DM + k0 + kf);
            Bs[kf + 0][row] = vb.x; Bs[kf + 1][row] = vb.y;
            Bs[kf + 2][row] = vb.z; Bs[kf + 3][row] = vb.w;
        }
        __syncthreads();
#pragma unroll 8
        for (int kk = 0; kk < 32; kk++) {
            float a[8], b[8];
            *(float4*)(a)     = *(const float4*)&As[kk][ty * 4];
            *(float4*)(a + 4) = *(const float4*)&As[kk][64 + ty * 4];
            *(float4*)(b)     = *(const float4*)&Bs[kk][tx * 4];
            *(float4*)(b + 4) = *(const float4*)&Bs[kk][64 + tx * 4];
#pragma unroll
            for (int i = 0; i < 8; i++)
#pragma unroll
                for (int j = 0; j < 8; j++)
                    acc[i][j] += a[i] * b[j];
        }
        __syncthreads();
    }

    float bv[8];
#pragma unroll
    for (int j = 0; j < 4; j++) {
        bv[j]     = bias[bn + tx * 4 + j];
        bv[j + 4] = bias[bn + 64 + tx * 4 + j];
    }
#pragma unroll
    for (int i = 0; i < 8; i++) {
        int m = bm + ((i < 4) ? (ty * 4 + i) : (60 + ty * 4 + i));
        float4 o0, o1;
        o0.x = acc[i][0] + bv[0]; o0.y = acc[i][1] + bv[1];
        o0.z = acc[i][2] + bv[2]; o0.w = acc[i][3] + bv[3];
        o1.x = acc[i][4] + bv[4]; o1.y = acc[i][5] + bv[5];
        o1.z = acc[i][6] + bv[6]; o1.w = acc[i][7] + bv[7];
        *(float4*)(C + (size_t)m * DM + bn + tx * 4)      = o0;
        *(float4*)(C + (size_t)m * DM + bn + 64 + tx * 4) = o1;
    }
}

// ---------------------------------------------------------------------------
// Flash attention (causal), fp32. One block = 64 query rows of one (b,h).
// 128 threads as a 16(ty) x 8(tx) grid; each thread owns a 4x8 S / O tile:
//   rows ty*4..ty*4+3 (16*4 = 64 rows), cols tx*8..tx*8+7 (8*8 = 64 cols).
// smem: Qs[64][64] | Kt[64][65] (aliased as P after S) | Vs[64][64]
// Q/K/V read from plain [b*2048+s][h*64+d] layout written by the QKV GEMM.
// ---------------------------------------------------------------------------
__global__ __launch_bounds__(128) void attn_kernel()
{
    extern __shared__ float smem[];
    float* Qs = smem;                       // 64*64
    float* Kt = smem + 64 * 64;             // 64*65 (transposed K; later P[m][n])
    float* Vs = smem + 64 * 64 + 64 * 65;   // 64*64

    const int t  = threadIdx.x;
    const int tx = t & 7;
    const int ty = t >> 3;      // 0..15
    const int qt = blockIdx.x;  // query tile 0..31
    const int bh = blockIdx.y;  // 0..63
    const int b  = bh >> 4;
    const int h  = bh & 15;

    const size_t base = (size_t)b * SEQ * DM + (size_t)h * HD;

    // Load Q tile, pre-scaled by 1/sqrt(64)
#pragma unroll
    for (int i = 0; i < 8; i++) {
        int idx = t + i * 128;
        int row = idx >> 4;
        int c   = (idx & 15) << 2;
        float4 v = *(const float4*)(g_Q + base + (size_t)(qt * 64 + row) * DM + c);
        v.x *= 0.125f; v.y *= 0.125f; v.z *= 0.125f; v.w *= 0.125f;
        *(float4*)&Qs[row * 64 + c] = v;
    }

    float O[4][8];
    float rmax[4], rsum[4];
#pragma unroll
    for (int i = 0; i < 4; i++) {
        rmax[i] = -1e30f;
        rsum[i] = 0.f;
#pragma unroll
        for (int c = 0; c < 8; c++) O[i][c] = 0.f;
    }

    for (int j = 0; j <= qt; j++) {
        __syncthreads();   // previous O-update done before overwriting Kt/Vs
#pragma unroll
        for (int i = 0; i < 8; i++) {
            int idx = t + i * 128;
            int row = idx >> 4;        // key index within tile
            int c   = (idx & 15) << 2; // head-dim offset
            float4 kv = *(const float4*)(g_K + base + (size_t)(j * 64 + row) * DM + c);
            Kt[(c + 0) * 65 + row] = kv.x;
            Kt[(c + 1) * 65 + row] = kv.y;
            Kt[(c + 2) * 65 + row] = kv.z;
            Kt[(c + 3) * 65 + row] = kv.w;
            float4 vv = *(const float4*)(g_V + base + (size_t)(j * 64 + row) * DM + c);
            *(float4*)&Vs[row * 64 + c] = vv;
        }
        __syncthreads();

        // S = (Q/sqrt(hd)) @ K^T   (4 rows x 8 cols per thread)
        float S[4][8];
#pragma unroll
        for (int i = 0; i < 4; i++)
#pragma unroll
            for (int jj = 0; jj < 8; jj++) S[i][jj] = 0.f;

#pragma unroll 4
        for (int d = 0; d < 64; d++) {
            float qv[4], kv[8];
#pragma unroll
            for (int i = 0; i < 4; i++)  qv[i]  = Qs[(ty * 4 + i) * 64 + d];
#pragma unroll
            for (int jj = 0; jj < 8; jj++) kv[jj] = Kt[d * 65 + tx * 8 + jj];
#pragma unroll
            for (int i = 0; i < 4; i++)
#pragma unroll
                for (int jj = 0; jj < 8; jj++)
                    S[i][jj] += qv[i] * kv[jj];
        }

        if (j == qt) {   // causal mask on the diagonal tile
#pragma unroll
            for (int i = 0; i < 4; i++)
#pragma unroll
                for (int jj = 0; jj < 8; jj++)
                    if (tx * 8 + jj > ty * 4 + i) S[i][jj] = -1e30f;
        }

        // Online softmax. Threads sharing a row are 8 consecutive lanes
        // (t = ty*8.. wait: same ty across tx=0..7 are consecutive t), so
        // xor-shuffles 1/2/4 reduce across the row's octet.
#pragma unroll
        for (int i = 0; i < 4; i++) {
            float mx = S[i][0];
#pragma unroll
            for (int jj = 1; jj < 8; jj++) mx = fmaxf(mx, S[i][jj]);
            mx = fmaxf(mx, __shfl_xor_sync(0xffffffffu, mx, 1));
            mx = fmaxf(mx, __shfl_xor_sync(0xffffffffu, mx, 2));
            mx = fmaxf(mx, __shfl_xor_sync(0xffffffffu, mx, 4));
            float mnew  = fmaxf(rmax[i], mx);
            float scale = __expf(rmax[i] - mnew);
            rmax[i] = mnew;
            float s = 0.f;
#pragma unroll
            for (int jj = 0; jj < 8; jj++) {
                S[i][jj] = __expf(S[i][jj] - mnew);
                s += S[i][jj];
            }
            s += __shfl_xor_sync(0xffffffffu, s, 1);
            s += __shfl_xor_sync(0xffffffffu, s, 2);
            s += __shfl_xor_sync(0xffffffffu, s, 4);
            rsum[i] = rsum[i] * scale + s;
#pragma unroll
            for (int c = 0; c < 8; c++) O[i][c] *= scale;
        }

        __syncthreads();   // everyone done reading Kt
        // P -> smem (alias over Kt), layout [m][n] stride 65
#pragma unroll
        for (int i = 0; i < 4; i++)
#pragma unroll
            for (int jj = 0; jj < 8; jj++)
                Kt[(ty * 4 + i) * 65 + tx * 8 + jj] = S[i][jj];
        __syncthreads();

        // O += P @ V
#pragma unroll 4
        for (int n = 0; n < 64; n++) {
            float pv[4], vv[8];
#pragma unroll
            for (int i = 0; i < 4; i++) pv[i] = Kt[(ty * 4 + i) * 65 + n];
#pragma unroll
            for (int c = 0; c < 8; c++) vv[c] = Vs[n * 64 + tx * 8 + c];
#pragma unroll
            for (int i = 0; i < 4; i++)
#pragma unroll
                for (int c = 0; c < 8; c++)
                    O[i][c] += pv[i] * vv[c];
        }
    }

    // Normalize and write to g_A in plain [b*2048+s][h*64+d] layout
#pragma unroll
    for (int i = 0; i < 4; i++) {
        float inv = 1.0f / rsum[i];
        int row = qt * 64 + ty * 4 + i;
        float4 o0, o1;
        o0.x = O[i][0] * inv; o0.y = O[i][1] * inv;
        o0.z = O[i][2] * inv; o0.w = O[i][3] * inv;
        o1.x = O[i][4] * inv; o1.y = O[i][5] * inv;
        o1.z = O[i][6] * inv; o1.w = O[i][7] * inv;
        *(float4*)(g_A + base + (size_t)row * DM + tx * 8)     = o0;
        *(float4*)(g_A + base + (size_t)row * DM + tx * 8 + 4) = o1;
    }
}

// ---------------------------------------------------------------------------
extern "C" void kernel_launch(void* const* d_in, const int* in_sizes, int n_in,
                              void* d_out, int out_size)
{
    // Size-driven input classification (robust to metadata ordering):
    //   8388608 elems -> x;  1048576 -> weights (Wq,Wk,Wv,Wo in order);
    //   1024 -> biases (bq,bk,bv,bo in order).
    const float* x = 0;
    const float* Ws[4] = {0, 0, 0, 0};
    const float* bs[4] = {0, 0, 0, 0};
    int nw = 0, nb = 0;
    for (int i = 0; i < n_in; i++) {
        if (in_sizes[i] == M_TOT * DM)      x = (const float*)d_in[i];
        else if (in_sizes[i] == DM * DM)    { if (nw < 4) Ws[nw++] = (const float*)d_in[i]; }
        else if (in_sizes[i] == DM)         { if (nb < 4) bs[nb++] = (const float*)d_in[i]; }
    }
    const float *Wq = Ws[0], *Wk = Ws[1], *Wv = Ws[2], *Wo = Ws[3];
    const float *bq = bs[0], *bk = bs[1], *bv = bs[2], *bo = bs[3];
    float* out = (float*)d_out;

    void *pQ, *pK, *pV, *pA;
    cudaGetSymbolAddress(&pQ, g_Q);
    cudaGetSymbolAddress(&pK, g_K);
    cudaGetSymbolAddress(&pV, g_V);
    cudaGetSymbolAddress(&pA, g_A);

    // 1) Fused Q/K/V projections
    gemm_xwt_kernel<<<dim3(M_TOT / 128, DM / 128, 3), 256>>>(
        x, Wq, Wk, Wv, bq, bk, bv, (float*)pQ, (float*)pK, (float*)pV);

    // 2) Causal flash attention
    const int attn_smem = (64 * 64 + 64 * 65 + 64 * 64) * (int)sizeof(float); // 49408 B
    cudaFuncSetAttribute(attn_kernel, cudaFuncAttributeMaxDynamicSharedMemorySize, attn_smem);
    attn_kernel<<<dim3(SEQ / 64, 4 * N_HEADS), 128, attn_smem>>>();

    // 3) Output projection -> d_out
    gemm_xwt_kernel<<<dim3(M_TOT / 128, DM / 128, 1), 256>>>(
        (const float*)pA, Wo, Wo, Wo, bo, bo, bo, out, out, out);
}